// round 1
// baseline (speedup 1.0000x reference)
#include <cuda_runtime.h>

// Rowwise cosine similarity.
// a, b: [16, 4096, 256] f32  ->  out: [16, 4096] f32
// out[r] = dot(a_r, b_r) * rsqrt(max(|a_r|^2, EPS)) * rsqrt(max(|b_r|^2, EPS))

#define EPS 1e-12f

__global__ __launch_bounds__(256, 8)
void cosine_rows_kernel(const float4* __restrict__ a,
                        const float4* __restrict__ b,
                        float* __restrict__ out,
                        int n_rows)
{
    // one warp per row; 8 warps per CTA
    const int warp_in_cta = threadIdx.x >> 5;
    const int lane        = threadIdx.x & 31;
    const int row         = blockIdx.x * 8 + warp_in_cta;
    if (row >= n_rows) return;

    // 256 floats per row = 64 float4; lane loads float4[lane] and float4[lane+32]
    const long long base = (long long)row * 64;

    float4 a0 = a[base + lane];
    float4 a1 = a[base + lane + 32];
    float4 b0 = b[base + lane];
    float4 b1 = b[base + lane + 32];

    float aa = a0.x*a0.x + a0.y*a0.y + a0.z*a0.z + a0.w*a0.w
             + a1.x*a1.x + a1.y*a1.y + a1.z*a1.z + a1.w*a1.w;
    float bb = b0.x*b0.x + b0.y*b0.y + b0.z*b0.z + b0.w*b0.w
             + b1.x*b1.x + b1.y*b1.y + b1.z*b1.z + b1.w*b1.w;
    float ab = a0.x*b0.x + a0.y*b0.y + a0.z*b0.z + a0.w*b0.w
             + a1.x*b1.x + a1.y*b1.y + a1.z*b1.z + a1.w*b1.w;

    // butterfly warp reduction of 3 floats
    #pragma unroll
    for (int off = 16; off > 0; off >>= 1) {
        aa += __shfl_xor_sync(0xFFFFFFFFu, aa, off);
        bb += __shfl_xor_sync(0xFFFFFFFFu, bb, off);
        ab += __shfl_xor_sync(0xFFFFFFFFu, ab, off);
    }

    if (lane == 0) {
        float inv_a = rsqrtf(fmaxf(aa, EPS));
        float inv_b = rsqrtf(fmaxf(bb, EPS));
        out[row] = ab * inv_a * inv_b;
    }
}

extern "C" void kernel_launch(void* const* d_in, const int* in_sizes, int n_in,
                              void* d_out, int out_size)
{
    const float4* a = (const float4*)d_in[0];
    const float4* b = (const float4*)d_in[1];
    float* out = (float*)d_out;

    // in_sizes[0] = 16*4096*256 elements; rows = elems / 256
    const int n_rows = in_sizes[0] / 256;   // 65536
    const int warps_per_cta = 8;
    const int n_blocks = (n_rows + warps_per_cta - 1) / warps_per_cta;

    cosine_rows_kernel<<<n_blocks, 256>>>(a, b, out, n_rows);
}